// round 1
// baseline (speedup 1.0000x reference)
#include <cuda_runtime.h>

namespace {
constexpr int T_STEPS = 64;
constexpr int S_DIM = 16;
constexpr int B_DIM = 2048;
constexpr int ZD = 64;
constexpr int SB = S_DIM * B_DIM;  // 32768 rows
constexpr int R = 64;              // rows per block
constexpr int NT = 256;            // threads per block
// dynamic smem: Wsh[64*64] + zshT[64*65] + dsh[64*64] + bsh[64] + red[8]
constexpr int SMEM_FLOATS = 4096 + 64 * 65 + 4096 + 64 + 8;
constexpr int SMEM_BYTES = SMEM_FLOATS * 4;
}

__device__ float g_cd[B_DIM * ZD];  // context @ Wc, [B, Z]

__global__ void ctx_kernel(const float* __restrict__ context,
                           const float* __restrict__ Wc) {
    int idx = blockIdx.x * blockDim.x + threadIdx.x;  // over B*Z
    int b = idx >> 6, z = idx & 63;
    float acc = 0.f;
#pragma unroll
    for (int c = 0; c < 64; ++c)
        acc = fmaf(context[b * 64 + c], Wc[c * 64 + z], acc);
    g_cd[idx] = acc;
}

__global__ void __launch_bounds__(NT, 4) scan_kernel(
    const float* __restrict__ z0, const float* __restrict__ eps,
    const float* __restrict__ W, const float* __restrict__ bvec,
    const float* __restrict__ sigmas, float* __restrict__ out) {
    extern __shared__ float smem[];
    float* Wsh  = smem;             // [64][64], row k = W[k][:]
    float* zshT = smem + 4096;      // [64][65], zshT[j*65+r] = z[r][j]
    float* dsh  = zshT + 64 * 65;   // [64][64], dsh[r*64+j] (drift / u_partial)
    float* bsh  = dsh + 4096;       // [64]
    float* red  = bsh + 64;         // [8]

    const int tid = threadIdx.x;
    const int r0 = blockIdx.x * R;
    const float dt = 1.0f / T_STEPS;
    const float sqrt_dt = 0.125f;  // sqrt(1/64)

    // load W into shared (coalesced)
#pragma unroll
    for (int k = 0; k < (64 * 64) / NT; ++k)
        Wsh[tid + k * NT] = W[tid + k * NT];

    // elementwise-phase mapping: fixed column j1, rows rb + 4k
    const int j1 = tid & 63;
    const int rb = tid >> 6;

    float* zs_out = out + 1;  // z_samples [T+1, S, B, Z]
    float cdv[16];            // ctx_drift for my 16 (r, j1) elements (const over t)
    float acc_lw = 0.f;       // accumulates e^2 + z0^2 - u^2 - zT^2

    // init: load z0, emit z_samples[0], boundary +z0^2, cache ctx drift
#pragma unroll
    for (int k = 0; k < 16; ++k) {
        int r = rb + 4 * k;
        size_t gi = (size_t)(r0 + r) * 64 + j1;
        float v = z0[gi];
        zshT[j1 * 65 + r] = v;
        zs_out[gi] = v;
        acc_lw += v * v;
        cdv[k] = g_cd[(((r0 + r) & (B_DIM - 1)) << 6) + j1];
    }
    __syncthreads();

    // GEMM mapping: 16x16 threads, 4x4 output tile each
    const int rg = (tid >> 4) * 4;
    const int cg = (tid & 15) * 4;

    // initial drift = z0 @ W
    {
        float acc[4][4] = {};
#pragma unroll 8
        for (int k = 0; k < 64; ++k) {
            float zr[4];
#pragma unroll
            for (int i = 0; i < 4; ++i) zr[i] = zshT[k * 65 + rg + i];
            const float4 w4 = *(const float4*)&Wsh[k * 64 + cg];
#pragma unroll
            for (int i = 0; i < 4; ++i) {
                acc[i][0] = fmaf(zr[i], w4.x, acc[i][0]);
                acc[i][1] = fmaf(zr[i], w4.y, acc[i][1]);
                acc[i][2] = fmaf(zr[i], w4.z, acc[i][2]);
                acc[i][3] = fmaf(zr[i], w4.w, acc[i][3]);
            }
        }
#pragma unroll
        for (int i = 0; i < 4; ++i)
#pragma unroll
            for (int q = 0; q < 4; ++q)
                dsh[(rg + i) * 64 + cg + q] = acc[i][q];
    }
    __syncthreads();

#pragma unroll 1
    for (int t = 0; t < T_STEPS; ++t) {
        const float sig = __ldg(&sigmas[t]);
        const float stdv = sig * sqrt_dt;
        const float inv_std = 1.0f / stdv;
        const float btj = __ldg(&bvec[t * 64 + j1]);
        if (tid < 64) bsh[tid] = bvec[t * 64 + tid];
        const float* eps_t = eps + (size_t)t * SB * 64;
        float* zo = zs_out + (size_t)(t + 1) * SB * 64;
        const bool last = (t == T_STEPS - 1);

        // phase 1: elementwise forward update (coalesced eps read / z write)
#pragma unroll
        for (int k = 0; k < 16; ++k) {
            int r = rb + 4 * k;
            size_t gi = (size_t)(r0 + r) * 64 + j1;
            float e = eps_t[gi];
            float zp = zshT[j1 * 65 + r];
            float d = dsh[r * 64 + j1];  // drift_prev = z_prev @ W
            float zn = zp + (d + cdv[k] + btj) * dt + stdv * e;
            zshT[j1 * 65 + r] = zn;
            zo[gi] = zn;
            dsh[r * 64 + j1] = (zp - zn) * inv_std;  // u_partial
            acc_lw += e * e;
            if (last) acc_lw -= zn * zn;  // boundary -zT^2
        }
        __syncthreads();

        // phase 2: drift_new = z @ W, epilogue computes u and -u^2
        const float dt_inv = dt * inv_std;
        float acc[4][4] = {};
#pragma unroll 8
        for (int k = 0; k < 64; ++k) {
            float zr[4];
#pragma unroll
            for (int i = 0; i < 4; ++i) zr[i] = zshT[k * 65 + rg + i];
            const float4 w4 = *(const float4*)&Wsh[k * 64 + cg];
#pragma unroll
            for (int i = 0; i < 4; ++i) {
                acc[i][0] = fmaf(zr[i], w4.x, acc[i][0]);
                acc[i][1] = fmaf(zr[i], w4.y, acc[i][1]);
                acc[i][2] = fmaf(zr[i], w4.z, acc[i][2]);
                acc[i][3] = fmaf(zr[i], w4.w, acc[i][3]);
            }
        }
#pragma unroll
        for (int i = 0; i < 4; ++i) {
#pragma unroll
            for (int q = 0; q < 4; ++q) {
                int rr = rg + i, cc = cg + q;
                float up = dsh[rr * 64 + cc];  // u_partial
                float u = up + (acc[i][q] + bsh[cc]) * dt_inv;
                acc_lw -= u * u;
                dsh[rr * 64 + cc] = acc[i][q];  // drift for next step
            }
        }
        __syncthreads();
    }

    // block-reduce acc_lw, add 0.5/S * sum into out[0]
#pragma unroll
    for (int off = 16; off; off >>= 1)
        acc_lw += __shfl_down_sync(0xffffffffu, acc_lw, off);
    if ((tid & 31) == 0) red[tid >> 5] = acc_lw;
    __syncthreads();
    if (tid == 0) {
        float s = 0.f;
#pragma unroll
        for (int w = 0; w < NT / 32; ++w) s += red[w];
        atomicAdd(out, (0.5f / S_DIM) * s);
    }
}

extern "C" void kernel_launch(void* const* d_in, const int* in_sizes, int n_in,
                              void* d_out, int out_size) {
    (void)in_sizes; (void)n_in; (void)out_size;
    const float* z0      = (const float*)d_in[0];
    const float* eps     = (const float*)d_in[1];
    const float* context = (const float*)d_in[2];
    const float* W       = (const float*)d_in[3];
    const float* Wc      = (const float*)d_in[4];
    const float* bvec    = (const float*)d_in[5];
    const float* sigmas  = (const float*)d_in[6];
    float* out = (float*)d_out;

    cudaFuncSetAttribute(scan_kernel,
                         cudaFuncAttributeMaxDynamicSharedMemorySize, SMEM_BYTES);
    cudaMemsetAsync(out, 0, sizeof(float));               // zero log_w accumulator
    ctx_kernel<<<(B_DIM * ZD) / 256, 256>>>(context, Wc); // g_cd = context @ Wc
    scan_kernel<<<SB / R, NT, SMEM_BYTES>>>(z0, eps, W, bvec, sigmas, out);
}

// round 2
// speedup vs baseline: 1.1455x; 1.1455x over previous
#include <cuda_runtime.h>

namespace {
constexpr int T_STEPS = 64;
constexpr int S_DIM = 16;
constexpr int B_DIM = 2048;
constexpr int SB = S_DIM * B_DIM;  // 32768 rows
constexpr int R = 64;              // rows per block
constexpr int NT = 128;            // threads per block
constexpr int PAD = 68;            // floats per transposed column (16B-aligned)
// smem: Wsh[64*64] + zshT[64*PAD] + dsh[64*PAD] + red[4]
constexpr int SMEM_FLOATS = 4096 + 2 * 64 * PAD + 4;
constexpr int SMEM_BYTES = SMEM_FLOATS * 4;
}

__device__ float g_cdT[64 * B_DIM];  // (context @ Wc) transposed: [Z][B]

__global__ void ctx_kernel(const float* __restrict__ context,
                           const float* __restrict__ Wc) {
    int idx = blockIdx.x * blockDim.x + threadIdx.x;  // over Z*B
    int z = idx >> 11, b = idx & (B_DIM - 1);
    float acc = 0.f;
#pragma unroll
    for (int c = 0; c < 64; ++c)
        acc = fmaf(context[b * 64 + c], Wc[c * 64 + z], acc);
    g_cdT[idx] = acc;  // coalesced write over b
}

__device__ __forceinline__ unsigned long long pack2(float x, float y) {
    unsigned long long r;
    asm("mov.b64 %0, {%1, %2};" : "=l"(r) : "f"(x), "f"(y));
    return r;
}
__device__ __forceinline__ void unpack2(unsigned long long v, float& x, float& y) {
    asm("mov.b64 {%0, %1}, %2;" : "=f"(x), "=f"(y) : "l"(v));
}
__device__ __forceinline__ void ffma2(unsigned long long& d, unsigned long long a,
                                      unsigned long long b) {
    asm("fma.rn.f32x2 %0, %1, %2, %0;" : "+l"(d) : "l"(a), "l"(b));
}

__global__ void __launch_bounds__(NT, 4) scan_kernel(
    const float* __restrict__ z0, const float* __restrict__ eps,
    const float* __restrict__ W, const float* __restrict__ bvec,
    const float* __restrict__ sigmas, float* __restrict__ out) {
    extern __shared__ float smem[];
    float* Wsh  = smem;               // [64][64]
    float* zshT = smem + 4096;        // [j][r] padded PAD
    float* dsh  = zshT + 64 * PAD;    // [j][r] drift / u_partial
    float* red  = dsh + 64 * PAD;     // [4]

    const int tid = threadIdx.x;
    const int r0 = blockIdx.x * R;
    const float dt = 1.0f / T_STEPS;
    const float sqrt_dt = 0.125f;

    // load W (coalesced float4)
    {
        const float4* Wg = (const float4*)W;
        float4* Ws4 = (float4*)Wsh;
#pragma unroll
        for (int k = 0; k < 8; ++k) Ws4[tid + k * NT] = Wg[tid + k * NT];
    }

    // phase-1 mapping: fixed column j1, rows rbase..rbase+31
    const int j1 = tid & 63;
    const int rbase = (tid >> 6) * 32;
    const int b0 = r0 & (B_DIM - 1);  // block's base batch index (mult of 64)

    float acc_lw = 0.f;  // accumulates e^2 + z0^2 - u^2 - zT^2
    float* zs_out = out + 1;

    // init: load z0, emit z_samples[0], boundary +z0^2
#pragma unroll
    for (int m = 0; m < 8; ++m) {
        int rr = rbase + 4 * m;
        float4 z4;
        size_t gbase = (size_t)(r0 + rr) * 64 + j1;
#pragma unroll
        for (int i = 0; i < 4; ++i) {
            float v = z0[gbase + (size_t)i * 64];
            ((float*)&z4)[i] = v;
            zs_out[gbase + (size_t)i * 64] = v;
            acc_lw += v * v;
        }
        *(float4*)(zshT + j1 * PAD + rr) = z4;
    }
    __syncthreads();

    // GEMM mapping: 16 row-groups (fast) x 8 col-groups, 4x8 tile per thread
    const int rg = (tid & 15) * 4;
    const int cg = (tid >> 4) * 8;

    // initial drift = z0 @ W -> dsh
    {
        unsigned long long acc[4][4] = {};
#pragma unroll 8
        for (int k = 0; k < 64; ++k) {
            float4 z4 = *(const float4*)(zshT + k * PAD + rg);
            ulonglong2 wa = *(const ulonglong2*)(Wsh + k * 64 + cg);
            ulonglong2 wb = *(const ulonglong2*)(Wsh + k * 64 + cg + 4);
            unsigned long long wp[4] = {wa.x, wa.y, wb.x, wb.y};
            unsigned long long zp[4] = {pack2(z4.x, z4.x), pack2(z4.y, z4.y),
                                        pack2(z4.z, z4.z), pack2(z4.w, z4.w)};
#pragma unroll
            for (int i = 0; i < 4; ++i)
#pragma unroll
                for (int q = 0; q < 4; ++q) ffma2(acc[i][q], zp[i], wp[q]);
        }
        float af[4][8];
#pragma unroll
        for (int i = 0; i < 4; ++i)
#pragma unroll
            for (int q = 0; q < 4; ++q) unpack2(acc[i][q], af[i][2 * q], af[i][2 * q + 1]);
#pragma unroll
        for (int c = 0; c < 8; ++c) {
            float4 dv = {af[0][c], af[1][c], af[2][c], af[3][c]};
            *(float4*)(dsh + (cg + c) * PAD + rg) = dv;
        }
    }
    __syncthreads();

#pragma unroll 1
    for (int t = 0; t < T_STEPS; ++t) {
        const float sig = __ldg(&sigmas[t]);
        const float stdv = sig * sqrt_dt;
        const float inv_std = 1.0f / stdv;
        const float btj = __ldg(&bvec[t * 64 + j1]);
        const float* eps_t = eps + (size_t)t * SB * 64;
        float* zo = zs_out + (size_t)(t + 1) * SB * 64;
        const bool last = (t == T_STEPS - 1);

        // ---- phase 1: elementwise forward update ----
#pragma unroll
        for (int m = 0; m < 8; ++m) {
            int rr = rbase + 4 * m;
            float4 zp4 = *(const float4*)(zshT + j1 * PAD + rr);
            float4 d4  = *(const float4*)(dsh + j1 * PAD + rr);
            float4 cd4 = *(const float4*)(g_cdT + j1 * B_DIM + b0 + rr);
            size_t gbase = (size_t)(r0 + rr) * 64 + j1;
            float e[4];
#pragma unroll
            for (int i = 0; i < 4; ++i) e[i] = __ldcs(eps_t + gbase + (size_t)i * 64);
            float4 zn4, up4;
#pragma unroll
            for (int i = 0; i < 4; ++i) {
                float zp = ((const float*)&zp4)[i];
                float mu = ((const float*)&d4)[i] + ((const float*)&cd4)[i] + btj;
                float zn = fmaf(stdv, e[i], fmaf(mu, dt, zp));
                ((float*)&zn4)[i] = zn;
                ((float*)&up4)[i] = (zp - zn) * inv_std;
                acc_lw += e[i] * e[i];
                if (last) acc_lw -= zn * zn;
            }
            *(float4*)(zshT + j1 * PAD + rr) = zn4;
            *(float4*)(dsh + j1 * PAD + rr) = up4;
#pragma unroll
            for (int i = 0; i < 4; ++i)
                __stcs(zo + gbase + (size_t)i * 64, ((const float*)&zn4)[i]);
        }
        __syncthreads();

        // ---- phase 2: drift_new = z @ W (f32x2 packed FMA) ----
        unsigned long long acc[4][4] = {};
#pragma unroll 8
        for (int k = 0; k < 64; ++k) {
            float4 z4 = *(const float4*)(zshT + k * PAD + rg);
            ulonglong2 wa = *(const ulonglong2*)(Wsh + k * 64 + cg);
            ulonglong2 wb = *(const ulonglong2*)(Wsh + k * 64 + cg + 4);
            unsigned long long wp[4] = {wa.x, wa.y, wb.x, wb.y};
            unsigned long long zp[4] = {pack2(z4.x, z4.x), pack2(z4.y, z4.y),
                                        pack2(z4.z, z4.z), pack2(z4.w, z4.w)};
#pragma unroll
            for (int i = 0; i < 4; ++i)
#pragma unroll
                for (int q = 0; q < 4; ++q) ffma2(acc[i][q], zp[i], wp[q]);
        }

        // epilogue: u = u_partial + (drift + b_t)*dt/std ; -u^2 ; store drift
        const float dt_inv = dt * inv_std;
        float af[4][8];
#pragma unroll
        for (int i = 0; i < 4; ++i)
#pragma unroll
            for (int q = 0; q < 4; ++q) unpack2(acc[i][q], af[i][2 * q], af[i][2 * q + 1]);
#pragma unroll
        for (int c = 0; c < 8; ++c) {
            int cc = cg + c;
            float bt = __ldg(&bvec[t * 64 + cc]);
            float4 up4 = *(const float4*)(dsh + cc * PAD + rg);
            float4 dv;
#pragma unroll
            for (int i = 0; i < 4; ++i) {
                float a = af[i][c];
                float u = fmaf(a + bt, dt_inv, ((const float*)&up4)[i]);
                acc_lw -= u * u;
                ((float*)&dv)[i] = a;
            }
            *(float4*)(dsh + cc * PAD + rg) = dv;
        }
        __syncthreads();
    }

    // block-reduce acc_lw, add 0.5/S * sum into out[0]
#pragma unroll
    for (int off = 16; off; off >>= 1)
        acc_lw += __shfl_down_sync(0xffffffffu, acc_lw, off);
    if ((tid & 31) == 0) red[tid >> 5] = acc_lw;
    __syncthreads();
    if (tid == 0) {
        float s = red[0] + red[1] + red[2] + red[3];
        atomicAdd(out, (0.5f / S_DIM) * s);
    }
}

extern "C" void kernel_launch(void* const* d_in, const int* in_sizes, int n_in,
                              void* d_out, int out_size) {
    (void)in_sizes; (void)n_in; (void)out_size;
    const float* z0      = (const float*)d_in[0];
    const float* eps     = (const float*)d_in[1];
    const float* context = (const float*)d_in[2];
    const float* W       = (const float*)d_in[3];
    const float* Wc      = (const float*)d_in[4];
    const float* bvec    = (const float*)d_in[5];
    const float* sigmas  = (const float*)d_in[6];
    float* out = (float*)d_out;

    cudaFuncSetAttribute(scan_kernel,
                         cudaFuncAttributeMaxDynamicSharedMemorySize, SMEM_BYTES);
    cudaMemsetAsync(out, 0, sizeof(float));
    ctx_kernel<<<(64 * B_DIM) / 256, 256>>>(context, Wc);  // g_cdT = (ctx @ Wc)^T
    scan_kernel<<<SB / R, NT, SMEM_BYTES>>>(z0, eps, W, bvec, sigmas, out);
}